// round 1
// baseline (speedup 1.0000x reference)
#include <cuda_runtime.h>
#include <cuda_bf16.h>

// LIF neuron: x_seq (T=64, B=32, F=8192) fp32 -> (spike_seq, mem_seq) each (T,B,F).
// Recurrence serial in T, independent per (b,f) lane. Pure streaming problem:
// 64 MiB in, 128 MiB out. DRAM-bound.

static constexpr int T  = 64;
static constexpr int BF = 32 * 8192;      // 262144 lanes
static constexpr int N4 = BF / 4;         // 65536 float4 lanes

__global__ __launch_bounds__(256) void lif_kernel(
    const float4* __restrict__ x,     // [T, N4]
    float*        __restrict__ out)   // [2, T, N4*4] : spike then mem
{
    const int lane = blockIdx.x * blockDim.x + threadIdx.x;

    float4* spike_out = reinterpret_cast<float4*>(out);
    float4* mem_out   = reinterpret_cast<float4*>(out) + (size_t)T * N4;

    float mx = 0.0f, my = 0.0f, mz = 0.0f, mw = 0.0f;

    #pragma unroll 8
    for (int t = 0; t < T; t++) {
        const float4 xv = __ldcs(&x[(size_t)t * N4 + lane]);

        // mem = mem*0.5 + x   (exact: *0.5 is an exponent shift, so fma == mul+add)
        mx = __fmaf_rn(mx, 0.5f, xv.x);
        my = __fmaf_rn(my, 0.5f, xv.y);
        mz = __fmaf_rn(mz, 0.5f, xv.z);
        mw = __fmaf_rn(mw, 0.5f, xv.w);

        float4 s;
        s.x = (mx >= 1.0f) ? 1.0f : 0.0f;
        s.y = (my >= 1.0f) ? 1.0f : 0.0f;
        s.z = (mz >= 1.0f) ? 1.0f : 0.0f;
        s.w = (mw >= 1.0f) ? 1.0f : 0.0f;

        // reset: mem = mem * (1 - spike)  (V_RESET = 0)
        mx = (s.x != 0.0f) ? 0.0f : mx;
        my = (s.y != 0.0f) ? 0.0f : my;
        mz = (s.z != 0.0f) ? 0.0f : mz;
        mw = (s.w != 0.0f) ? 0.0f : mw;

        float4 m = {mx, my, mz, mw};

        __stcs(&spike_out[(size_t)t * N4 + lane], s);
        __stcs(&mem_out  [(size_t)t * N4 + lane], m);
    }
}

extern "C" void kernel_launch(void* const* d_in, const int* in_sizes, int n_in,
                              void* d_out, int out_size) {
    const float4* x = reinterpret_cast<const float4*>(d_in[0]);
    float* out = reinterpret_cast<float*>(d_out);

    const int threads = 256;
    const int blocks  = N4 / threads;   // 256 blocks
    lif_kernel<<<blocks, threads>>>(x, out);
}

// round 2
// speedup vs baseline: 1.3540x; 1.3540x over previous
#include <cuda_runtime.h>
#include <cuda_bf16.h>

// LIF neuron: x_seq (T=64, B=32, F=8192) fp32 -> (spike_seq, mem_seq) each (T,B,F).
// Serial in T per lane; pure streaming (64 MiB in, 128 MiB out) -> DRAM-bound.
// R1: explicit 8-deep register prefetch ring to force MLP=8 per thread
// (previous version had MLP~1.5, latency-bound at 38.9% DRAM).

static constexpr int T  = 64;
static constexpr int BF = 32 * 8192;      // 262144 lanes
static constexpr int N4 = BF / 4;         // 65536 float4 lanes
static constexpr int PF = 8;              // prefetch depth (outstanding LDG.128 per thread)

__global__ __launch_bounds__(256) void lif_kernel(
    const float4* __restrict__ x,     // [T, N4]
    float*        __restrict__ out)   // [2, T, N4*4] : spike then mem
{
    const int lane = blockIdx.x * blockDim.x + threadIdx.x;

    float4* spike_out = reinterpret_cast<float4*>(out);
    float4* mem_out   = reinterpret_cast<float4*>(out) + (size_t)T * N4;

    // Prime the prefetch ring: 8 LDG.128 in flight before any compute.
    float4 buf[PF];
    #pragma unroll
    for (int i = 0; i < PF; i++)
        buf[i] = __ldcs(&x[(size_t)i * N4 + lane]);

    float mx = 0.0f, my = 0.0f, mz = 0.0f, mw = 0.0f;

    #pragma unroll
    for (int t = 0; t < T; t++) {
        const float4 xv = buf[t % PF];

        // Refill this slot immediately -> keep 8 loads outstanding.
        if (t + PF < T)
            buf[t % PF] = __ldcs(&x[(size_t)(t + PF) * N4 + lane]);

        // mem = mem*0.5 + x   (*0.5 is exact, fma == mul+add bitwise)
        mx = __fmaf_rn(mx, 0.5f, xv.x);
        my = __fmaf_rn(my, 0.5f, xv.y);
        mz = __fmaf_rn(mz, 0.5f, xv.z);
        mw = __fmaf_rn(mw, 0.5f, xv.w);

        float4 s;
        s.x = (mx >= 1.0f) ? 1.0f : 0.0f;
        s.y = (my >= 1.0f) ? 1.0f : 0.0f;
        s.z = (mz >= 1.0f) ? 1.0f : 0.0f;
        s.w = (mw >= 1.0f) ? 1.0f : 0.0f;

        // reset: mem = 0 where spiked (V_RESET = 0)
        mx = (s.x != 0.0f) ? 0.0f : mx;
        my = (s.y != 0.0f) ? 0.0f : my;
        mz = (s.z != 0.0f) ? 0.0f : mz;
        mw = (s.w != 0.0f) ? 0.0f : mw;

        const float4 m = {mx, my, mz, mw};

        __stcs(&spike_out[(size_t)t * N4 + lane], s);
        __stcs(&mem_out  [(size_t)t * N4 + lane], m);
    }
}

extern "C" void kernel_launch(void* const* d_in, const int* in_sizes, int n_in,
                              void* d_out, int out_size) {
    const float4* x = reinterpret_cast<const float4*>(d_in[0]);
    float* out = reinterpret_cast<float*>(d_out);

    const int threads = 256;
    const int blocks  = N4 / threads;   // 256 blocks
    lif_kernel<<<blocks, threads>>>(x, out);
}

// round 3
// speedup vs baseline: 1.3762x; 1.0164x over previous
#include <cuda_runtime.h>
#include <cuda_bf16.h>

// LIF neuron: x_seq (T=64, B=32, F=8192) fp32 -> (spike_seq, mem_seq) each (T,B,F).
// R2 -> R3 changes:
//  - reads __ldcg (keep x resident in 126MB L2 across graph replays; x = 64 MiB)
//  - writes stay __stcs (evict-first: the 128 MiB write stream self-evicts
//    instead of displacing x)
//  - 64-thread blocks -> 1024 blocks over 148 SMs (6.92 avg vs 7 max, ~1%
//    imbalance; previous 256-block grid had a 2-vs-1 blocks/SM tail)

static constexpr int T  = 64;
static constexpr int BF = 32 * 8192;      // 262144 lanes
static constexpr int N4 = BF / 4;         // 65536 float4 lanes
static constexpr int PF = 8;              // outstanding LDG.128 per thread

__global__ __launch_bounds__(64) void lif_kernel(
    const float4* __restrict__ x,     // [T, N4]
    float*        __restrict__ out)   // [2, T, N4*4] : spike then mem
{
    const int lane = blockIdx.x * 64 + threadIdx.x;

    float4* spike_out = reinterpret_cast<float4*>(out);
    float4* mem_out   = reinterpret_cast<float4*>(out) + (size_t)T * N4;

    // Prime the prefetch ring: 8 LDG.128 in flight before any compute.
    // __ldcg: skip L1 (no reuse there), cache in L2 (reuse across replays).
    float4 buf[PF];
    #pragma unroll
    for (int i = 0; i < PF; i++)
        buf[i] = __ldcg(&x[(size_t)i * N4 + lane]);

    float mx = 0.0f, my = 0.0f, mz = 0.0f, mw = 0.0f;

    #pragma unroll
    for (int t = 0; t < T; t++) {
        const float4 xv = buf[t % PF];

        if (t + PF < T)
            buf[t % PF] = __ldcg(&x[(size_t)(t + PF) * N4 + lane]);

        // mem = mem*0.5 + x   (*0.5 is exact, fma == mul+add bitwise)
        mx = __fmaf_rn(mx, 0.5f, xv.x);
        my = __fmaf_rn(my, 0.5f, xv.y);
        mz = __fmaf_rn(mz, 0.5f, xv.z);
        mw = __fmaf_rn(mw, 0.5f, xv.w);

        float4 s;
        s.x = (mx >= 1.0f) ? 1.0f : 0.0f;
        s.y = (my >= 1.0f) ? 1.0f : 0.0f;
        s.z = (mz >= 1.0f) ? 1.0f : 0.0f;
        s.w = (mw >= 1.0f) ? 1.0f : 0.0f;

        // reset: mem = 0 where spiked (V_RESET = 0)
        mx = (s.x != 0.0f) ? 0.0f : mx;
        my = (s.y != 0.0f) ? 0.0f : my;
        mz = (s.z != 0.0f) ? 0.0f : mz;
        mw = (s.w != 0.0f) ? 0.0f : mw;

        const float4 m = {mx, my, mz, mw};

        __stcs(&spike_out[(size_t)t * N4 + lane], s);
        __stcs(&mem_out  [(size_t)t * N4 + lane], m);
    }
}

extern "C" void kernel_launch(void* const* d_in, const int* in_sizes, int n_in,
                              void* d_out, int out_size) {
    const float4* x = reinterpret_cast<const float4*>(d_in[0]);
    float* out = reinterpret_cast<float*>(d_out);

    const int threads = 64;
    const int blocks  = N4 / threads;   // 1024 blocks
    lif_kernel<<<blocks, threads>>>(x, out);
}